// round 2
// baseline (speedup 1.0000x reference)
#include <cuda_runtime.h>
#include <math_constants.h>

// ---------------------------------------------------------------------------
// AffineChamferLoss via EXACT uniform-grid nearest neighbor.
//
// K0: zero cell heads, bbox atomics, out
// K1: affine-transform moving pts, store both sets as float4, block-reduced
//     bbox (ordered-uint atomicMin/Max) per set
// K2: bin points into per-cell linked lists (atomicExch head, next in node.w)
// K3: per-query expanding Chebyshev-ring exact NN search + mean reduction
// ---------------------------------------------------------------------------

#define NMAX   16384
#define CAP    262144         // max cells per set (64^3)
#define TCELLS 131072.0f      // target cell count

__device__ float4   g_xbuf[NMAX];    // transformed moving pts (queries dir0)
__device__ float4   g_ybuf[NMAX];    // fixed pts              (queries dir1)
__device__ float4   g_nodeA[NMAX];   // fixed-set nodes: x,y,z,next(bits)
__device__ float4   g_nodeB[NMAX];   // mov-set nodes
__device__ int      g_headA[CAP];    // cell heads, fixed set
__device__ int      g_headB[CAP];    // cell heads, mov set
__device__ unsigned g_bbox[12];      // [set*6 + (0..2 min | 3..5 max)] ordered

// ---- order-preserving float<->uint ----------------------------------------
__device__ __forceinline__ unsigned f2ord(float f) {
    unsigned u = __float_as_uint(f);
    return (u & 0x80000000u) ? ~u : (u | 0x80000000u);
}
__device__ __forceinline__ float ord2f(unsigned u) {
    return (u & 0x80000000u) ? __uint_as_float(u & 0x7fffffffu)
                             : __uint_as_float(~u);
}

// ---- grid geometry (deterministic pure function of bbox) -------------------
struct GInfo {
    float mnx, mny, mnz, h, invh;
    int gx, gy, gz;
};

__device__ __forceinline__ GInfo make_grid(int s) {
    const unsigned* bb = g_bbox + s * 6;
    GInfo g;
    g.mnx = ord2f(bb[0]); g.mny = ord2f(bb[1]); g.mnz = ord2f(bb[2]);
    float mxx = ord2f(bb[3]), mxy = ord2f(bb[4]), mxz = ord2f(bb[5]);
    float ex = fmaxf(mxx - g.mnx, 1e-4f);
    float ey = fmaxf(mxy - g.mny, 1e-4f);
    float ez = fmaxf(mxz - g.mnz, 1e-4f);
    float h = cbrtf(ex * ey * ez * (1.0f / TCELLS));
    int gx = 1, gy = 1, gz = 1;
    for (int it = 0; it < 32; ++it) {
        gx = (int)(ex / h) + 1;
        gy = (int)(ey / h) + 1;
        gz = (int)(ez / h) + 1;
        if ((long long)gx * (long long)gy * (long long)gz <= (long long)CAP) break;
        h *= 1.3f;
    }
    g.h = h; g.invh = 1.0f / h;
    g.gx = gx; g.gy = gy; g.gz = gz;
    return g;
}

// ---------------------------------------------------------------------------
__global__ void init_kernel(float* out) {
    int i = blockIdx.x * blockDim.x + threadIdx.x;
    if (i < CAP) { g_headA[i] = -1; g_headB[i] = -1; }
    if (i == 0) out[0] = 0.0f;
    if (i < 12) g_bbox[i] = ((i % 6) < 3) ? 0xFFFFFFFFu : 0u;
}

// transform + bbox
__global__ void prep_kernel(const float* __restrict__ fx,
                            const float* __restrict__ mv,
                            const float* __restrict__ mat,
                            const float* __restrict__ tr,
                            int nf, int nm) {
    __shared__ unsigned sbb[12];
    int t = threadIdx.x;
    if (t < 12) sbb[t] = ((t % 6) < 3) ? 0xFFFFFFFFu : 0u;
    __syncthreads();

    int i = blockIdx.x * blockDim.x + t;

    // mov point (set 1): ordered-min neutral = 0xFFFFFFFF, max neutral = 0
    unsigned mvmn[3] = {0xFFFFFFFFu, 0xFFFFFFFFu, 0xFFFFFFFFu};
    unsigned mvmx[3] = {0u, 0u, 0u};
    if (i < nm) {
        float p0 = mv[3*i+0], p1 = mv[3*i+1], p2 = mv[3*i+2];
        float x0 = fmaf(p2, mat[6], fmaf(p1, mat[3], fmaf(p0, mat[0], tr[0])));
        float x1 = fmaf(p2, mat[7], fmaf(p1, mat[4], fmaf(p0, mat[1], tr[1])));
        float x2 = fmaf(p2, mat[8], fmaf(p1, mat[5], fmaf(p0, mat[2], tr[2])));
        g_xbuf[i] = make_float4(x0, x1, x2, 0.0f);
        mvmn[0] = mvmx[0] = f2ord(x0);
        mvmn[1] = mvmx[1] = f2ord(x1);
        mvmn[2] = mvmx[2] = f2ord(x2);
    }
    unsigned fxmn[3] = {0xFFFFFFFFu, 0xFFFFFFFFu, 0xFFFFFFFFu};
    unsigned fxmx[3] = {0u, 0u, 0u};
    if (i < nf) {
        float y0 = fx[3*i+0], y1 = fx[3*i+1], y2 = fx[3*i+2];
        g_ybuf[i] = make_float4(y0, y1, y2, 0.0f);
        fxmn[0] = fxmx[0] = f2ord(y0);
        fxmn[1] = fxmx[1] = f2ord(y1);
        fxmn[2] = fxmx[2] = f2ord(y2);
    }

    // warp reduce, lane0 -> smem atomics
#pragma unroll
    for (int a = 0; a < 3; a++) {
        fxmn[a] = __reduce_min_sync(0xffffffffu, fxmn[a]);
        fxmx[a] = __reduce_max_sync(0xffffffffu, fxmx[a]);
        mvmn[a] = __reduce_min_sync(0xffffffffu, mvmn[a]);
        mvmx[a] = __reduce_max_sync(0xffffffffu, mvmx[a]);
    }
    if ((t & 31) == 0) {
#pragma unroll
        for (int a = 0; a < 3; a++) {
            atomicMin(&sbb[a],     fxmn[a]);  // set 0 = fixed
            atomicMax(&sbb[3 + a], fxmx[a]);
            atomicMin(&sbb[6 + a], mvmn[a]);  // set 1 = mov
            atomicMax(&sbb[9 + a], mvmx[a]);
        }
    }
    __syncthreads();
    if (t < 6)  atomicMin(&g_bbox[t], sbb[t]);        // handles both sets' mins/maxes:
    if (t >= 6 && t < 12) { /* split below */ }
    if (t < 12) {
        if ((t % 6) < 3) atomicMin(&g_bbox[t], sbb[t]);
        else             atomicMax(&g_bbox[t], sbb[t]);
    }
}

// bin points into linked lists
__global__ void bin_kernel(int nf, int nm) {
    int i = blockIdx.x * blockDim.x + threadIdx.x;
    GInfo ga = make_grid(0);   // fixed set grid
    GInfo gb = make_grid(1);   // mov set grid
    if (i < nf) {
        float4 p = g_ybuf[i];
        int ix = min(ga.gx - 1, max(0, (int)((p.x - ga.mnx) * ga.invh)));
        int iy = min(ga.gy - 1, max(0, (int)((p.y - ga.mny) * ga.invh)));
        int iz = min(ga.gz - 1, max(0, (int)((p.z - ga.mnz) * ga.invh)));
        int cell = (ix * ga.gy + iy) * ga.gz + iz;
        int old = atomicExch(&g_headA[cell], i);
        g_nodeA[i] = make_float4(p.x, p.y, p.z, __int_as_float(old));
    }
    if (i < nm) {
        float4 p = g_xbuf[i];
        int ix = min(gb.gx - 1, max(0, (int)((p.x - gb.mnx) * gb.invh)));
        int iy = min(gb.gy - 1, max(0, (int)((p.y - gb.mny) * gb.invh)));
        int iz = min(gb.gz - 1, max(0, (int)((p.z - gb.mnz) * gb.invh)));
        int cell = (ix * gb.gy + iy) * gb.gz + iz;
        int old = atomicExch(&g_headB[cell], i);
        g_nodeB[i] = make_float4(p.x, p.y, p.z, __int_as_float(old));
    }
}

// exact grid NN + mean reduction
__global__ void __launch_bounds__(128)
query_kernel(float* out, int nm, int nf) {
    const int dir = blockIdx.y;                  // 0: mov->fixed, 1: fixed->mov
    const int nq = dir ? nf : nm;
    const float4* __restrict__ qb    = dir ? g_ybuf  : g_xbuf;
    const float4* __restrict__ nodes = dir ? g_nodeB : g_nodeA;
    const int*    __restrict__ head  = dir ? g_headB : g_headA;
    GInfo gi = make_grid(dir ? 1 : 0);

    int qi = blockIdx.x * blockDim.x + threadIdx.x;
    float acc = 0.0f;
    if (qi < nq) {
        float4 q = qb[qi];
        float rx = (q.x - gi.mnx) * gi.invh;
        float ry = (q.y - gi.mny) * gi.invh;
        float rz = (q.z - gi.mnz) * gi.invh;
        int cx = (int)floorf(rx); float fxr = rx - (float)cx;
        int cy = (int)floorf(ry); float fyr = ry - (float)cy;
        int cz = (int)floorf(rz); float fzr = rz - (float)cz;
        // distance (cell units) from q to nearest wall of its virtual cell
        float fmin3 = fminf(fminf(fminf(fxr, 1.0f - fxr), fminf(fyr, 1.0f - fyr)),
                            fminf(fzr, 1.0f - fzr));

        // max ring needed to cover the whole grid from this virtual cell
        int rmx = max(max(max(cx, gi.gx - 1 - cx), max(cy, gi.gy - 1 - cy)),
                      max(cz, gi.gz - 1 - cz)) + 1;

        float best = CUDART_INF_F;
        float h2 = gi.h * gi.h;

        for (int r = 0; r <= rmx; ++r) {
            if (r >= 1) {
                float b = ((float)(r - 1) + fmin3) * gi.h;
                if (b * b >= best) break;
            }
            for (int a = -r; a <= r; ++a) {
                int ix = cx + a;
                if (ix < 0 || ix >= gi.gx) continue;
                float ddx = (a > 0) ? ((float)a - fxr)
                          : (a < 0) ? ((float)(-a - 1) + fxr) : 0.0f;
                int aa = abs(a);
                for (int b = -r; b <= r; ++b) {
                    int iy = cy + b;
                    if (iy < 0 || iy >= gi.gy) continue;
                    int ab = max(aa, abs(b));
                    float ddy = (b > 0) ? ((float)b - fyr)
                              : (b < 0) ? ((float)(-b - 1) + fyr) : 0.0f;
                    float dxy2 = ddx * ddx + ddy * ddy;
                    for (int c = -r; c <= r; ++c) {
                        if (max(ab, abs(c)) != r) continue;     // shell only
                        int iz = cz + c;
                        if (iz < 0 || iz >= gi.gz) continue;
                        float ddz = (c > 0) ? ((float)c - fzr)
                                  : (c < 0) ? ((float)(-c - 1) + fzr) : 0.0f;
                        float cd2 = (dxy2 + ddz * ddz) * h2;
                        if (cd2 >= best) continue;              // exact cell prune
                        int idx = head[(ix * gi.gy + iy) * gi.gz + iz];
                        while (idx >= 0) {
                            float4 nd = nodes[idx];
                            float dx = nd.x - q.x;
                            float dy = nd.y - q.y;
                            float dz = nd.z - q.z;
                            float d2 = fmaf(dx, dx, fmaf(dy, dy, dz * dz));
                            best = fminf(best, d2);
                            idx = __float_as_int(nd.w);
                        }
                    }
                }
            }
        }
        acc = best / (float)nq;
    }

    // block reduce + atomicAdd
#pragma unroll
    for (int o = 16; o; o >>= 1) acc += __shfl_down_sync(0xffffffffu, acc, o);
    __shared__ float ws[4];
    int lane = threadIdx.x & 31, warp = threadIdx.x >> 5;
    if (lane == 0) ws[warp] = acc;
    __syncthreads();
    if (warp == 0) {
        acc = (lane < 4) ? ws[lane] : 0.0f;
#pragma unroll
        for (int o = 2; o; o >>= 1) acc += __shfl_down_sync(0xffffffffu, acc, o);
        if (lane == 0) atomicAdd(out, acc);
    }
}

// ---------------------------------------------------------------------------
extern "C" void kernel_launch(void* const* d_in, const int* in_sizes, int n_in,
                              void* d_out, int out_size) {
    const float* fx  = (const float*)d_in[0];  // pts_fixed [N_FIX,3]
    const float* mv  = (const float*)d_in[1];  // pts_mov   [N_MOV,3]
    const float* mat = (const float*)d_in[2];  // [1,3,3]
    const float* tr  = (const float*)d_in[3];  // [1,3,1]
    float* out = (float*)d_out;

    int nf = in_sizes[0] / 3;
    int nm = in_sizes[1] / 3;
    int nmax = nf > nm ? nf : nm;

    init_kernel<<<(CAP + 511) / 512, 512>>>(out);
    prep_kernel<<<(nmax + 255) / 256, 256>>>(fx, mv, mat, tr, nf, nm);
    bin_kernel<<<(nmax + 255) / 256, 256>>>(nf, nm);

    dim3 qgrid((nmax + 127) / 128, 2);
    query_kernel<<<qgrid, 128>>>(out, nm, nf);
}

// round 3
// speedup vs baseline: 10.4860x; 10.4860x over previous
#include <cuda_runtime.h>
#include <math_constants.h>

// ---------------------------------------------------------------------------
// AffineChamferLoss via EXACT uniform-grid NN with CSR counting sort.
//
// K1 prep:    affine transform, per-block bbox partials, zero counts/out
// K2 grid:    reduce bbox partials, derive per-set grid geometry
// K3 count:   per-point cell id + count atomics
// K4-K6 scan: multi-block exclusive scan of cell counts -> cellStart + cursor
// K7 scatter: points into CSR order
// K8 query:   expanding Chebyshev shells, clipped, z-strip merged point scans,
//             exterior-aware stop bound; mean-reduce both directions
// ---------------------------------------------------------------------------

#define NMAX  16384
#define CAP   262144          // cells per set (scan sized to this)
#define SBLK  256             // scan blocks per set (CAP/1024)
#define SPAD  (CAP + 16)      // padded row stride (16B-aligned rows)
#define INFF  3.0e38f

__device__ float4   g_xbuf[NMAX];          // transformed moving pts (set 1)
__device__ float4   g_ybuf[NMAX];          // fixed pts              (set 0)
__device__ int      g_cell[2][NMAX];
__device__ unsigned g_cnt[2][CAP];
__device__ int      g_startArr[2][SPAD];   // CSR starts (+ total at [CAP])
__device__ unsigned g_cur[2][CAP];         // scatter cursors
__device__ float4   g_sort[2][NMAX];       // CSR-sorted points
__device__ unsigned g_bpart[2][128][6];    // per-prep-block bbox partials
__device__ unsigned g_bsum[2][SBLK];
__device__ unsigned g_bscan[2][SBLK];

struct GridI { float mnx, mny, mnz, h, invh; int gx, gy, gz, pad; };
__device__ GridI g_grid[2];

// ---- order-preserving float<->uint ----------------------------------------
__device__ __forceinline__ unsigned f2ord(float f) {
    unsigned u = __float_as_uint(f);
    return (u & 0x80000000u) ? ~u : (u | 0x80000000u);
}
__device__ __forceinline__ float ord2f(unsigned u) {
    return (u & 0x80000000u) ? __uint_as_float(u & 0x7fffffffu)
                             : __uint_as_float(~u);
}

// ---- 256-thread block exclusive scan (one value per thread) ----------------
__device__ __forceinline__ unsigned excl_scan_256(unsigned v, unsigned* wsm) {
    int lane = threadIdx.x & 31, wp = threadIdx.x >> 5;
    unsigned inc = v;
#pragma unroll
    for (int o = 1; o < 32; o <<= 1) {
        unsigned n = __shfl_up_sync(0xffffffffu, inc, o);
        if (lane >= o) inc += n;
    }
    if (lane == 31) wsm[wp] = inc;
    __syncthreads();
    if (wp == 0) {
        unsigned ws = (lane < 8) ? wsm[lane] : 0u;
#pragma unroll
        for (int o = 1; o < 8; o <<= 1) {
            unsigned n = __shfl_up_sync(0xffffffffu, ws, o);
            if (lane >= o) ws += n;
        }
        if (lane < 8) wsm[lane] = ws;
    }
    __syncthreads();
    unsigned off = wp ? wsm[wp - 1] : 0u;
    return off + inc - v;
}

// ---------------------------------------------------------------------------
// K1: transform + bbox partials + zero counts/out
__global__ void prep_kernel(const float* __restrict__ fx,
                            const float* __restrict__ mv,
                            const float* __restrict__ mat,
                            const float* __restrict__ tr,
                            int nf, int nm, float* out, int nblocks) {
    __shared__ unsigned sbb[12];
    int t = threadIdx.x;
    if (t < 12) sbb[t] = ((t % 6) < 3) ? 0xFFFFFFFFu : 0u;
    __syncthreads();

    int i = blockIdx.x * 256 + t;

    unsigned mvmn[3] = {0xFFFFFFFFu, 0xFFFFFFFFu, 0xFFFFFFFFu};
    unsigned mvmx[3] = {0u, 0u, 0u};
    if (i < nm) {
        float p0 = mv[3*i+0], p1 = mv[3*i+1], p2 = mv[3*i+2];
        float x0 = fmaf(p2, mat[6], fmaf(p1, mat[3], fmaf(p0, mat[0], tr[0])));
        float x1 = fmaf(p2, mat[7], fmaf(p1, mat[4], fmaf(p0, mat[1], tr[1])));
        float x2 = fmaf(p2, mat[8], fmaf(p1, mat[5], fmaf(p0, mat[2], tr[2])));
        g_xbuf[i] = make_float4(x0, x1, x2, 0.0f);
        mvmn[0] = mvmx[0] = f2ord(x0);
        mvmn[1] = mvmx[1] = f2ord(x1);
        mvmn[2] = mvmx[2] = f2ord(x2);
    }
    unsigned fxmn[3] = {0xFFFFFFFFu, 0xFFFFFFFFu, 0xFFFFFFFFu};
    unsigned fxmx[3] = {0u, 0u, 0u};
    if (i < nf) {
        float y0 = fx[3*i+0], y1 = fx[3*i+1], y2 = fx[3*i+2];
        g_ybuf[i] = make_float4(y0, y1, y2, 0.0f);
        fxmn[0] = fxmx[0] = f2ord(y0);
        fxmn[1] = fxmx[1] = f2ord(y1);
        fxmn[2] = fxmx[2] = f2ord(y2);
    }

#pragma unroll
    for (int a = 0; a < 3; a++) {
        fxmn[a] = __reduce_min_sync(0xffffffffu, fxmn[a]);
        fxmx[a] = __reduce_max_sync(0xffffffffu, fxmx[a]);
        mvmn[a] = __reduce_min_sync(0xffffffffu, mvmn[a]);
        mvmx[a] = __reduce_max_sync(0xffffffffu, mvmx[a]);
    }
    if ((t & 31) == 0) {
#pragma unroll
        for (int a = 0; a < 3; a++) {
            atomicMin(&sbb[a],     fxmn[a]);
            atomicMax(&sbb[3 + a], fxmx[a]);
            atomicMin(&sbb[6 + a], mvmn[a]);
            atomicMax(&sbb[9 + a], mvmx[a]);
        }
    }
    __syncthreads();
    if (t < 12) g_bpart[t / 6][blockIdx.x][t % 6] = sbb[t];

    // zero counts (flat over both sets)
    unsigned* cn = &g_cnt[0][0];
    int tid = blockIdx.x * 256 + t;
    int stride = nblocks * 256;
    for (int k = tid; k < 2 * CAP; k += stride) cn[k] = 0u;
    if (tid == 0) out[0] = 0.0f;
}

// K2: reduce bbox partials, build grid geometry (384 threads, 1 block)
__global__ void grid_kernel(int nblocks) {
    __shared__ unsigned bb[12];
    int t = threadIdx.x;
    int slot = t >> 5, lane = t & 31;
    if (slot < 12) {
        int s = slot / 6, k = slot % 6;
        bool ismin = (k < 3);
        unsigned v = ismin ? 0xFFFFFFFFu : 0u;
        for (int j = lane; j < nblocks; j += 32) {
            unsigned p = g_bpart[s][j][k];
            v = ismin ? min(v, p) : max(v, p);
        }
        v = ismin ? __reduce_min_sync(0xffffffffu, v)
                  : __reduce_max_sync(0xffffffffu, v);
        if (lane == 0) bb[slot] = v;
    }
    __syncthreads();
    if (t < 2) {
        int s = t;
        float mn0 = ord2f(bb[s*6+0]), mn1 = ord2f(bb[s*6+1]), mn2 = ord2f(bb[s*6+2]);
        float mx0 = ord2f(bb[s*6+3]), mx1 = ord2f(bb[s*6+4]), mx2 = ord2f(bb[s*6+5]);
        float ex = fmaxf(mx0 - mn0, 1e-4f);
        float ey = fmaxf(mx1 - mn1, 1e-4f);
        float ez = fmaxf(mx2 - mn2, 1e-4f);
        float h = cbrtf(ex * ey * ez * (1.0f / (0.70f * (float)CAP)));
        int gx = 1, gy = 1, gz = 1;
        for (int it = 0; it < 48; ++it) {
            gx = (int)(ex / h) + 1;
            gy = (int)(ey / h) + 1;
            gz = (int)(ez / h) + 1;
            if ((long long)gx * (long long)gy * (long long)gz <= (long long)CAP) break;
            h *= 1.12f;
        }
        GridI gi;
        gi.mnx = mn0; gi.mny = mn1; gi.mnz = mn2;
        gi.h = h; gi.invh = 1.0f / h;
        gi.gx = gx; gi.gy = gy; gi.gz = gz; gi.pad = 0;
        g_grid[s] = gi;
    }
}

// K3: cell ids + counts
__global__ void count_kernel(int nf, int nm) {
    int i = blockIdx.x * blockDim.x + threadIdx.x;
    GridI a = g_grid[0], b = g_grid[1];
    if (i < nf) {
        float4 p = g_ybuf[i];
        int ix = min(a.gx - 1, max(0, (int)((p.x - a.mnx) * a.invh)));
        int iy = min(a.gy - 1, max(0, (int)((p.y - a.mny) * a.invh)));
        int iz = min(a.gz - 1, max(0, (int)((p.z - a.mnz) * a.invh)));
        int c = (ix * a.gy + iy) * a.gz + iz;
        g_cell[0][i] = c;
        atomicAdd(&g_cnt[0][c], 1u);
    }
    if (i < nm) {
        float4 p = g_xbuf[i];
        int ix = min(b.gx - 1, max(0, (int)((p.x - b.mnx) * b.invh)));
        int iy = min(b.gy - 1, max(0, (int)((p.y - b.mny) * b.invh)));
        int iz = min(b.gz - 1, max(0, (int)((p.z - b.mnz) * b.invh)));
        int c = (ix * b.gy + iy) * b.gz + iz;
        g_cell[1][i] = c;
        atomicAdd(&g_cnt[1][c], 1u);
    }
}

// K4: per-block sums (grid: SBLK x 2, 256 threads, 1024 counts/block)
__global__ void scan1_kernel() {
    __shared__ unsigned sm[8];
    int s = blockIdx.y;
    const uint4* c4 = reinterpret_cast<const uint4*>(&g_cnt[s][0]);
    uint4 v = c4[blockIdx.x * 256 + threadIdx.x];
    unsigned tot = v.x + v.y + v.z + v.w;
    int lane = threadIdx.x & 31, wp = threadIdx.x >> 5;
#pragma unroll
    for (int o = 16; o; o >>= 1) tot += __shfl_down_sync(0xffffffffu, tot, o);
    if (lane == 0) sm[wp] = tot;
    __syncthreads();
    if (wp == 0) {
        unsigned w = (lane < 8) ? sm[lane] : 0u;
#pragma unroll
        for (int o = 4; o; o >>= 1) w += __shfl_down_sync(0xffffffffu, w, o);
        if (lane == 0) g_bsum[s][blockIdx.x] = w;
    }
}

// K5: scan block sums (1 block, 256 threads)
__global__ void scan2_kernel() {
    __shared__ unsigned wsm[8];
    for (int s = 0; s < 2; ++s) {
        unsigned v = g_bsum[s][threadIdx.x];
        unsigned e = excl_scan_256(v, wsm);
        g_bscan[s][threadIdx.x] = e;
        if (threadIdx.x == 255) g_startArr[s][CAP] = (int)(e + v);
        __syncthreads();
    }
}

// K6: local scans + write starts & cursors
__global__ void scan3_kernel() {
    __shared__ unsigned wsm[8];
    int s = blockIdx.y;
    const uint4* c4 = reinterpret_cast<const uint4*>(&g_cnt[s][0]);
    int vi = blockIdx.x * 256 + threadIdx.x;
    uint4 v = c4[vi];
    unsigned p1 = v.x, p2 = v.x + v.y, p3 = p2 + v.z, tot = p3 + v.w;
    unsigned e = excl_scan_256(tot, wsm);
    unsigned off = g_bscan[s][blockIdx.x] + e;
    int4 st = make_int4((int)off, (int)(off + p1), (int)(off + p2), (int)(off + p3));
    reinterpret_cast<int4*>(&g_startArr[s][0])[vi] = st;
    reinterpret_cast<int4*>(&g_cur[s][0])[vi] =
        make_int4(st.x, st.y, st.z, st.w);
}

// K7: scatter into CSR order
__global__ void scatter_kernel(int nf, int nm) {
    int i = blockIdx.x * blockDim.x + threadIdx.x;
    if (i < nf) {
        int c = g_cell[0][i];
        unsigned p = atomicAdd(&g_cur[0][c], 1u);
        g_sort[0][p] = g_ybuf[i];
    }
    if (i < nm) {
        int c = g_cell[1][i];
        unsigned p = atomicAdd(&g_cur[1][c], 1u);
        g_sort[1][p] = g_xbuf[i];
    }
}

// K8: exact NN query + mean reduction. dir0: mov->fixed, dir1: fixed->mov
__global__ void __launch_bounds__(128)
query_kernel(float* out, int nm, int nf) {
    const int dir = blockIdx.y;
    const int nq = dir ? nf : nm;
    const float4* __restrict__ qb  = g_sort[1 - dir];  // sorted queries
    const float4* __restrict__ tgt = g_sort[dir];
    const int*    __restrict__ cs  = &g_startArr[dir][0];
    GridI gi = g_grid[dir];

    int qi = blockIdx.x * 128 + threadIdx.x;
    float acc = 0.0f;
    if (qi < nq) {
        float4 q = qb[qi];
        int cx = min(gi.gx - 1, max(0, (int)floorf((q.x - gi.mnx) * gi.invh)));
        int cy = min(gi.gy - 1, max(0, (int)floorf((q.y - gi.mny) * gi.invh)));
        int cz = min(gi.gz - 1, max(0, (int)floorf((q.z - gi.mnz) * gi.invh)));
        int rmx = max(max(max(cx, gi.gx - 1 - cx), max(cy, gi.gy - 1 - cy)),
                      max(cz, gi.gz - 1 - cz));

        float best = INFF;
        for (int r = 0; r <= rmx; ++r) {
            if (r >= 1) {
                // min distance from q to any cell outside scanned box (radius r-1)
                int rm1 = r - 1;
                float bnd = INFF;
                if (cx - rm1 > 0)
                    bnd = fminf(bnd, q.x - fmaf((float)(cx - rm1), gi.h, gi.mnx));
                if (cx + rm1 < gi.gx - 1)
                    bnd = fminf(bnd, fmaf((float)(cx + rm1 + 1), gi.h, gi.mnx) - q.x);
                if (cy - rm1 > 0)
                    bnd = fminf(bnd, q.y - fmaf((float)(cy - rm1), gi.h, gi.mny));
                if (cy + rm1 < gi.gy - 1)
                    bnd = fminf(bnd, fmaf((float)(cy + rm1 + 1), gi.h, gi.mny) - q.y);
                if (cz - rm1 > 0)
                    bnd = fminf(bnd, q.z - fmaf((float)(cz - rm1), gi.h, gi.mnz));
                if (cz + rm1 < gi.gz - 1)
                    bnd = fminf(bnd, fmaf((float)(cz + rm1 + 1), gi.h, gi.mnz) - q.z);
                if (bnd * bnd >= best) break;   // also breaks when box covers grid
            }
            // scan Chebyshev shell r (clipped), z-strips merged
            int xlo = max(cx - r, 0), xhi = min(cx + r, gi.gx - 1);
            for (int ix = xlo; ix <= xhi; ++ix) {
                int adx = abs(ix - cx);
                float lox = fmaf((float)ix, gi.h, gi.mnx);
                float ddx = fmaxf(0.f, fmaxf(lox - q.x, q.x - (lox + gi.h)));
                float dx2 = ddx * ddx;
                if (dx2 >= best) continue;
                int ylo = max(cy - r, 0), yhi = min(cy + r, gi.gy - 1);
                for (int iy = ylo; iy <= yhi; ++iy) {
                    int ady = max(adx, abs(iy - cy));
                    float loy = fmaf((float)iy, gi.h, gi.mny);
                    float ddy = fmaxf(0.f, fmaxf(loy - q.y, q.y - (loy + gi.h)));
                    float dxy2 = fmaf(ddy, ddy, dx2);
                    if (dxy2 >= best) continue;
                    int base = (ix * gi.gy + iy) * gi.gz;
                    if (ady == r) {
                        // full z strip, one contiguous CSR range
                        int zlo = max(cz - r, 0), zhi = min(cz + r, gi.gz - 1);
                        int s0 = cs[base + zlo], e0 = cs[base + zhi + 1];
                        for (int p = s0; p < e0; ++p) {
                            float4 tp = tgt[p];
                            float ax = tp.x - q.x, ay = tp.y - q.y, az = tp.z - q.z;
                            float d2 = fmaf(ax, ax, fmaf(ay, ay, az * az));
                            best = fminf(best, d2);
                        }
                    } else {
                        // two cap cells at z = cz +/- r
                        int zc = cz - r;
                        if (zc >= 0) {
                            float loz = fmaf((float)zc, gi.h, gi.mnz);
                            float ddz = fmaxf(0.f, fmaxf(loz - q.z, q.z - (loz + gi.h)));
                            if (fmaf(ddz, ddz, dxy2) < best) {
                                int s0 = cs[base + zc], e0 = cs[base + zc + 1];
                                for (int p = s0; p < e0; ++p) {
                                    float4 tp = tgt[p];
                                    float ax = tp.x - q.x, ay = tp.y - q.y, az = tp.z - q.z;
                                    float d2 = fmaf(ax, ax, fmaf(ay, ay, az * az));
                                    best = fminf(best, d2);
                                }
                            }
                        }
                        zc = cz + r;
                        if (zc <= gi.gz - 1) {
                            float loz = fmaf((float)zc, gi.h, gi.mnz);
                            float ddz = fmaxf(0.f, fmaxf(loz - q.z, q.z - (loz + gi.h)));
                            if (fmaf(ddz, ddz, dxy2) < best) {
                                int s0 = cs[base + zc], e0 = cs[base + zc + 1];
                                for (int p = s0; p < e0; ++p) {
                                    float4 tp = tgt[p];
                                    float ax = tp.x - q.x, ay = tp.y - q.y, az = tp.z - q.z;
                                    float d2 = fmaf(ax, ax, fmaf(ay, ay, az * az));
                                    best = fminf(best, d2);
                                }
                            }
                        }
                    }
                }
            }
        }
        acc = best / (float)nq;
    }

    // block reduce + atomicAdd
#pragma unroll
    for (int o = 16; o; o >>= 1) acc += __shfl_down_sync(0xffffffffu, acc, o);
    __shared__ float ws[4];
    int lane = threadIdx.x & 31, warp = threadIdx.x >> 5;
    if (lane == 0) ws[warp] = acc;
    __syncthreads();
    if (warp == 0) {
        acc = (lane < 4) ? ws[lane] : 0.0f;
#pragma unroll
        for (int o = 2; o; o >>= 1) acc += __shfl_down_sync(0xffffffffu, acc, o);
        if (lane == 0) atomicAdd(out, acc);
    }
}

// ---------------------------------------------------------------------------
extern "C" void kernel_launch(void* const* d_in, const int* in_sizes, int n_in,
                              void* d_out, int out_size) {
    const float* fx  = (const float*)d_in[0];
    const float* mv  = (const float*)d_in[1];
    const float* mat = (const float*)d_in[2];
    const float* tr  = (const float*)d_in[3];
    float* out = (float*)d_out;

    int nf = in_sizes[0] / 3;
    int nm = in_sizes[1] / 3;
    int nmax = nf > nm ? nf : nm;
    int pblk = (nmax + 255) / 256;
    if (pblk > 128) pblk = 128;  // g_bpart capacity (nmax<=32768 covered)

    prep_kernel<<<pblk, 256>>>(fx, mv, mat, tr, nf, nm, out, pblk);
    grid_kernel<<<1, 384>>>(pblk);
    count_kernel<<<pblk, 256>>>(nf, nm);
    scan1_kernel<<<dim3(SBLK, 2), 256>>>();
    scan2_kernel<<<1, 256>>>();
    scan3_kernel<<<dim3(SBLK, 2), 256>>>();
    scatter_kernel<<<pblk, 256>>>(nf, nm);
    query_kernel<<<dim3((nmax + 127) / 128, 2), 128>>>(out, nm, nf);
}

// round 4
// speedup vs baseline: 64.7297x; 6.1730x over previous
#include <cuda_runtime.h>
#include <math_constants.h>

// ---------------------------------------------------------------------------
// AffineChamferLoss via EXACT uniform-grid NN (CSR counting sort) with
// ring-capped search + warp-cooperative brute-force fallback for tail queries.
// ---------------------------------------------------------------------------

#define NMAX  16384
#define CAP   131072          // cells per set
#define SBLK  128             // scan blocks per set (CAP/1024)
#define SPAD  (CAP + 16)
#define INFF  3.0e38f
#define RCAP  4               // max ring before deferring to brute force

__device__ float4   g_xbuf[NMAX];          // transformed moving pts (set 1)
__device__ float4   g_ybuf[NMAX];          // fixed pts              (set 0)
__device__ int      g_cell[2][NMAX];
__device__ unsigned g_cnt[2][CAP];
__device__ int      g_startArr[2][SPAD];
__device__ unsigned g_cur[2][CAP];
__device__ float4   g_sort[2][NMAX];
__device__ unsigned g_bpart[2][128][6];
__device__ unsigned g_bsum[2][SBLK];
__device__ unsigned g_bscan[2][SBLK];
__device__ int      g_defer[2][NMAX];
__device__ int      g_dcount[2];

struct GridI { float mnx, mny, mnz, h, invh; int gx, gy, gz, pad; };
__device__ GridI g_grid[2];

// ---- order-preserving float<->uint ----------------------------------------
__device__ __forceinline__ unsigned f2ord(float f) {
    unsigned u = __float_as_uint(f);
    return (u & 0x80000000u) ? ~u : (u | 0x80000000u);
}
__device__ __forceinline__ float ord2f(unsigned u) {
    return (u & 0x80000000u) ? __uint_as_float(u & 0x7fffffffu)
                             : __uint_as_float(~u);
}

// ---- 256-thread block exclusive scan ---------------------------------------
__device__ __forceinline__ unsigned excl_scan_256(unsigned v, unsigned* wsm) {
    int lane = threadIdx.x & 31, wp = threadIdx.x >> 5;
    unsigned inc = v;
#pragma unroll
    for (int o = 1; o < 32; o <<= 1) {
        unsigned n = __shfl_up_sync(0xffffffffu, inc, o);
        if (lane >= o) inc += n;
    }
    if (lane == 31) wsm[wp] = inc;
    __syncthreads();
    if (wp == 0) {
        unsigned ws = (lane < 8) ? wsm[lane] : 0u;
#pragma unroll
        for (int o = 1; o < 8; o <<= 1) {
            unsigned n = __shfl_up_sync(0xffffffffu, ws, o);
            if (lane >= o) ws += n;
        }
        if (lane < 8) wsm[lane] = ws;
    }
    __syncthreads();
    unsigned off = wp ? wsm[wp - 1] : 0u;
    return off + inc - v;
}

// ---------------------------------------------------------------------------
// K1: transform + bbox partials + zero counts/out/defer
__global__ void prep_kernel(const float* __restrict__ fx,
                            const float* __restrict__ mv,
                            const float* __restrict__ mat,
                            const float* __restrict__ tr,
                            int nf, int nm, float* out, int nblocks) {
    __shared__ unsigned sbb[12];
    int t = threadIdx.x;
    if (t < 12) sbb[t] = ((t % 6) < 3) ? 0xFFFFFFFFu : 0u;
    __syncthreads();

    int i = blockIdx.x * 256 + t;

    unsigned mvmn[3] = {0xFFFFFFFFu, 0xFFFFFFFFu, 0xFFFFFFFFu};
    unsigned mvmx[3] = {0u, 0u, 0u};
    if (i < nm) {
        float p0 = mv[3*i+0], p1 = mv[3*i+1], p2 = mv[3*i+2];
        float x0 = fmaf(p2, mat[6], fmaf(p1, mat[3], fmaf(p0, mat[0], tr[0])));
        float x1 = fmaf(p2, mat[7], fmaf(p1, mat[4], fmaf(p0, mat[1], tr[1])));
        float x2 = fmaf(p2, mat[8], fmaf(p1, mat[5], fmaf(p0, mat[2], tr[2])));
        g_xbuf[i] = make_float4(x0, x1, x2, 0.0f);
        mvmn[0] = mvmx[0] = f2ord(x0);
        mvmn[1] = mvmx[1] = f2ord(x1);
        mvmn[2] = mvmx[2] = f2ord(x2);
    }
    unsigned fxmn[3] = {0xFFFFFFFFu, 0xFFFFFFFFu, 0xFFFFFFFFu};
    unsigned fxmx[3] = {0u, 0u, 0u};
    if (i < nf) {
        float y0 = fx[3*i+0], y1 = fx[3*i+1], y2 = fx[3*i+2];
        g_ybuf[i] = make_float4(y0, y1, y2, 0.0f);
        fxmn[0] = fxmx[0] = f2ord(y0);
        fxmn[1] = fxmx[1] = f2ord(y1);
        fxmn[2] = fxmx[2] = f2ord(y2);
    }

#pragma unroll
    for (int a = 0; a < 3; a++) {
        fxmn[a] = __reduce_min_sync(0xffffffffu, fxmn[a]);
        fxmx[a] = __reduce_max_sync(0xffffffffu, fxmx[a]);
        mvmn[a] = __reduce_min_sync(0xffffffffu, mvmn[a]);
        mvmx[a] = __reduce_max_sync(0xffffffffu, mvmx[a]);
    }
    if ((t & 31) == 0) {
#pragma unroll
        for (int a = 0; a < 3; a++) {
            atomicMin(&sbb[a],     fxmn[a]);
            atomicMax(&sbb[3 + a], fxmx[a]);
            atomicMin(&sbb[6 + a], mvmn[a]);
            atomicMax(&sbb[9 + a], mvmx[a]);
        }
    }
    __syncthreads();
    if (t < 12) g_bpart[t / 6][blockIdx.x][t % 6] = sbb[t];

    unsigned* cn = &g_cnt[0][0];
    int tid = blockIdx.x * 256 + t;
    int stride = nblocks * 256;
    for (int k = tid; k < 2 * CAP; k += stride) cn[k] = 0u;
    if (tid == 0) { out[0] = 0.0f; g_dcount[0] = 0; g_dcount[1] = 0; }
}

// K2: reduce bbox partials, build grid geometry
__global__ void grid_kernel(int nblocks) {
    __shared__ unsigned bb[12];
    int t = threadIdx.x;
    int slot = t >> 5, lane = t & 31;
    if (slot < 12) {
        int s = slot / 6, k = slot % 6;
        bool ismin = (k < 3);
        unsigned v = ismin ? 0xFFFFFFFFu : 0u;
        for (int j = lane; j < nblocks; j += 32) {
            unsigned p = g_bpart[s][j][k];
            v = ismin ? min(v, p) : max(v, p);
        }
        v = ismin ? __reduce_min_sync(0xffffffffu, v)
                  : __reduce_max_sync(0xffffffffu, v);
        if (lane == 0) bb[slot] = v;
    }
    __syncthreads();
    if (t < 2) {
        int s = t;
        float mn0 = ord2f(bb[s*6+0]), mn1 = ord2f(bb[s*6+1]), mn2 = ord2f(bb[s*6+2]);
        float mx0 = ord2f(bb[s*6+3]), mx1 = ord2f(bb[s*6+4]), mx2 = ord2f(bb[s*6+5]);
        float ex = fmaxf(mx0 - mn0, 1e-4f);
        float ey = fmaxf(mx1 - mn1, 1e-4f);
        float ez = fmaxf(mx2 - mn2, 1e-4f);
        float h = cbrtf(ex * ey * ez * (1.0f / (0.75f * (float)CAP)));
        int gx = 1, gy = 1, gz = 1;
        for (int it = 0; it < 48; ++it) {
            gx = (int)(ex / h) + 1;
            gy = (int)(ey / h) + 1;
            gz = (int)(ez / h) + 1;
            if ((long long)gx * (long long)gy * (long long)gz <= (long long)CAP) break;
            h *= 1.12f;
        }
        GridI gi;
        gi.mnx = mn0; gi.mny = mn1; gi.mnz = mn2;
        gi.h = h; gi.invh = 1.0f / h;
        gi.gx = gx; gi.gy = gy; gi.gz = gz; gi.pad = 0;
        g_grid[s] = gi;
    }
}

// K3: cell ids + counts
__global__ void count_kernel(int nf, int nm) {
    int i = blockIdx.x * blockDim.x + threadIdx.x;
    GridI a = g_grid[0], b = g_grid[1];
    if (i < nf) {
        float4 p = g_ybuf[i];
        int ix = min(a.gx - 1, max(0, (int)((p.x - a.mnx) * a.invh)));
        int iy = min(a.gy - 1, max(0, (int)((p.y - a.mny) * a.invh)));
        int iz = min(a.gz - 1, max(0, (int)((p.z - a.mnz) * a.invh)));
        int c = (ix * a.gy + iy) * a.gz + iz;
        g_cell[0][i] = c;
        atomicAdd(&g_cnt[0][c], 1u);
    }
    if (i < nm) {
        float4 p = g_xbuf[i];
        int ix = min(b.gx - 1, max(0, (int)((p.x - b.mnx) * b.invh)));
        int iy = min(b.gy - 1, max(0, (int)((p.y - b.mny) * b.invh)));
        int iz = min(b.gz - 1, max(0, (int)((p.z - b.mnz) * b.invh)));
        int c = (ix * b.gy + iy) * b.gz + iz;
        g_cell[1][i] = c;
        atomicAdd(&g_cnt[1][c], 1u);
    }
}

// K4: per-block sums (grid SBLK x 2, 256 threads, 1024 counts/block)
__global__ void scan1_kernel() {
    __shared__ unsigned sm[8];
    int s = blockIdx.y;
    const uint4* c4 = reinterpret_cast<const uint4*>(&g_cnt[s][0]);
    uint4 v = c4[blockIdx.x * 256 + threadIdx.x];
    unsigned tot = v.x + v.y + v.z + v.w;
    int lane = threadIdx.x & 31, wp = threadIdx.x >> 5;
#pragma unroll
    for (int o = 16; o; o >>= 1) tot += __shfl_down_sync(0xffffffffu, tot, o);
    if (lane == 0) sm[wp] = tot;
    __syncthreads();
    if (wp == 0) {
        unsigned w = (lane < 8) ? sm[lane] : 0u;
#pragma unroll
        for (int o = 4; o; o >>= 1) w += __shfl_down_sync(0xffffffffu, w, o);
        if (lane == 0) g_bsum[s][blockIdx.x] = w;
    }
}

// K5: scan SBLK block sums per set (1 block, 128 threads, 4 warps)
__global__ void scan2_kernel() {
    __shared__ unsigned wsm[4];
    int lane = threadIdx.x & 31, wp = threadIdx.x >> 5;
    for (int s = 0; s < 2; ++s) {
        unsigned v = g_bsum[s][threadIdx.x];
        unsigned inc = v;
#pragma unroll
        for (int o = 1; o < 32; o <<= 1) {
            unsigned n = __shfl_up_sync(0xffffffffu, inc, o);
            if (lane >= o) inc += n;
        }
        if (lane == 31) wsm[wp] = inc;
        __syncthreads();
        if (wp == 0) {
            unsigned ws = (lane < 4) ? wsm[lane] : 0u;
#pragma unroll
            for (int o = 1; o < 4; o <<= 1) {
                unsigned n = __shfl_up_sync(0xffffffffu, ws, o);
                if (lane >= o) ws += n;
            }
            if (lane < 4) wsm[lane] = ws;
        }
        __syncthreads();
        unsigned off = wp ? wsm[wp - 1] : 0u;
        unsigned e = off + inc - v;
        g_bscan[s][threadIdx.x] = e;
        if (threadIdx.x == SBLK - 1) g_startArr[s][CAP] = (int)(e + v);
        __syncthreads();
    }
}

// K6: local scans + write starts & cursors
__global__ void scan3_kernel() {
    __shared__ unsigned wsm[8];
    int s = blockIdx.y;
    const uint4* c4 = reinterpret_cast<const uint4*>(&g_cnt[s][0]);
    int vi = blockIdx.x * 256 + threadIdx.x;
    uint4 v = c4[vi];
    unsigned p1 = v.x, p2 = v.x + v.y, p3 = p2 + v.z, tot = p3 + v.w;
    unsigned e = excl_scan_256(tot, wsm);
    unsigned off = g_bscan[s][blockIdx.x] + e;
    int4 st = make_int4((int)off, (int)(off + p1), (int)(off + p2), (int)(off + p3));
    reinterpret_cast<int4*>(&g_startArr[s][0])[vi] = st;
    reinterpret_cast<int4*>(&g_cur[s][0])[vi] = make_int4(st.x, st.y, st.z, st.w);
}

// K7: scatter into CSR order
__global__ void scatter_kernel(int nf, int nm) {
    int i = blockIdx.x * blockDim.x + threadIdx.x;
    if (i < nf) {
        int c = g_cell[0][i];
        unsigned p = atomicAdd(&g_cur[0][c], 1u);
        g_sort[0][p] = g_ybuf[i];
    }
    if (i < nm) {
        int c = g_cell[1][i];
        unsigned p = atomicAdd(&g_cur[1][c], 1u);
        g_sort[1][p] = g_xbuf[i];
    }
}

// K8: ring-capped exact NN + mean reduction; hard queries -> defer list
__global__ void __launch_bounds__(128)
query_kernel(float* out, int nm, int nf) {
    const int dir = blockIdx.y;
    const int nq = dir ? nf : nm;
    const float4* __restrict__ qb  = g_sort[1 - dir];
    const float4* __restrict__ tgt = g_sort[dir];
    const int*    __restrict__ cs  = &g_startArr[dir][0];
    GridI gi = g_grid[dir];

    int qi = blockIdx.x * 128 + threadIdx.x;
    float acc = 0.0f;
    if (qi < nq) {
        float4 q = qb[qi];
        int cx = min(gi.gx - 1, max(0, (int)floorf((q.x - gi.mnx) * gi.invh)));
        int cy = min(gi.gy - 1, max(0, (int)floorf((q.y - gi.mny) * gi.invh)));
        int cz = min(gi.gz - 1, max(0, (int)floorf((q.z - gi.mnz) * gi.invh)));
        int rmx = max(max(max(cx, gi.gx - 1 - cx), max(cy, gi.gy - 1 - cy)),
                      max(cz, gi.gz - 1 - cz));

        float best = INFF;
        bool deferred = false;
        for (int r = 0;; ++r) {
            if (r >= 1) {
                int rm1 = r - 1;
                float bnd = INFF;
                if (cx - rm1 > 0)
                    bnd = fminf(bnd, q.x - fmaf((float)(cx - rm1), gi.h, gi.mnx));
                if (cx + rm1 < gi.gx - 1)
                    bnd = fminf(bnd, fmaf((float)(cx + rm1 + 1), gi.h, gi.mnx) - q.x);
                if (cy - rm1 > 0)
                    bnd = fminf(bnd, q.y - fmaf((float)(cy - rm1), gi.h, gi.mny));
                if (cy + rm1 < gi.gy - 1)
                    bnd = fminf(bnd, fmaf((float)(cy + rm1 + 1), gi.h, gi.mny) - q.y);
                if (cz - rm1 > 0)
                    bnd = fminf(bnd, q.z - fmaf((float)(cz - rm1), gi.h, gi.mnz));
                if (cz + rm1 < gi.gz - 1)
                    bnd = fminf(bnd, fmaf((float)(cz + rm1 + 1), gi.h, gi.mnz) - q.z);
                if (bnd * bnd >= best) break;   // exact termination (INF when done)
            }
            if (r > rmx) break;                 // whole grid scanned
            if (r > RCAP) { deferred = true; break; }

            int xlo = max(cx - r, 0), xhi = min(cx + r, gi.gx - 1);
            for (int ix = xlo; ix <= xhi; ++ix) {
                int adx = abs(ix - cx);
                float lox = fmaf((float)ix, gi.h, gi.mnx);
                float ddx = fmaxf(0.f, fmaxf(lox - q.x, q.x - (lox + gi.h)));
                float dx2 = ddx * ddx;
                if (dx2 >= best) continue;
                int ylo = max(cy - r, 0), yhi = min(cy + r, gi.gy - 1);
                for (int iy = ylo; iy <= yhi; ++iy) {
                    int ady = max(adx, abs(iy - cy));
                    float loy = fmaf((float)iy, gi.h, gi.mny);
                    float ddy = fmaxf(0.f, fmaxf(loy - q.y, q.y - (loy + gi.h)));
                    float dxy2 = fmaf(ddy, ddy, dx2);
                    if (dxy2 >= best) continue;
                    int base = (ix * gi.gy + iy) * gi.gz;
                    if (ady == r) {
                        int zlo = max(cz - r, 0), zhi = min(cz + r, gi.gz - 1);
                        int s0 = cs[base + zlo], e0 = cs[base + zhi + 1];
                        for (int p = s0; p < e0; ++p) {
                            float4 tp = tgt[p];
                            float ax = tp.x - q.x, ay = tp.y - q.y, az = tp.z - q.z;
                            float d2 = fmaf(ax, ax, fmaf(ay, ay, az * az));
                            best = fminf(best, d2);
                        }
                    } else {
                        int zc = cz - r;
                        if (zc >= 0) {
                            float loz = fmaf((float)zc, gi.h, gi.mnz);
                            float ddz = fmaxf(0.f, fmaxf(loz - q.z, q.z - (loz + gi.h)));
                            if (fmaf(ddz, ddz, dxy2) < best) {
                                int s0 = cs[base + zc], e0 = cs[base + zc + 1];
                                for (int p = s0; p < e0; ++p) {
                                    float4 tp = tgt[p];
                                    float ax = tp.x - q.x, ay = tp.y - q.y, az = tp.z - q.z;
                                    float d2 = fmaf(ax, ax, fmaf(ay, ay, az * az));
                                    best = fminf(best, d2);
                                }
                            }
                        }
                        zc = cz + r;
                        if (zc <= gi.gz - 1) {
                            float loz = fmaf((float)zc, gi.h, gi.mnz);
                            float ddz = fmaxf(0.f, fmaxf(loz - q.z, q.z - (loz + gi.h)));
                            if (fmaf(ddz, ddz, dxy2) < best) {
                                int s0 = cs[base + zc], e0 = cs[base + zc + 1];
                                for (int p = s0; p < e0; ++p) {
                                    float4 tp = tgt[p];
                                    float ax = tp.x - q.x, ay = tp.y - q.y, az = tp.z - q.z;
                                    float d2 = fmaf(ax, ax, fmaf(ay, ay, az * az));
                                    best = fminf(best, d2);
                                }
                            }
                        }
                    }
                }
            }
        }
        if (deferred) {
            int slot = atomicAdd(&g_dcount[dir], 1);
            g_defer[dir][slot] = qi;
            acc = 0.0f;
        } else {
            acc = best / (float)nq;
        }
    }

#pragma unroll
    for (int o = 16; o; o >>= 1) acc += __shfl_down_sync(0xffffffffu, acc, o);
    __shared__ float ws[4];
    int lane = threadIdx.x & 31, warp = threadIdx.x >> 5;
    if (lane == 0) ws[warp] = acc;
    __syncthreads();
    if (warp == 0) {
        acc = (lane < 4) ? ws[lane] : 0.0f;
#pragma unroll
        for (int o = 2; o; o >>= 1) acc += __shfl_down_sync(0xffffffffu, acc, o);
        if (lane == 0) atomicAdd(out, acc);
    }
}

// K9: warp-per-query exhaustive NN for deferred queries
__global__ void __launch_bounds__(256)
brute_kernel(float* out, int nm, int nf) {
    int gw = (blockIdx.x * 256 + threadIdx.x) >> 5;
    int lane = threadIdx.x & 31;
    int nwarps = (gridDim.x * 256) >> 5;
    for (int dir = 0; dir < 2; ++dir) {
        int cnt = g_dcount[dir];
        int nq = dir ? nf : nm;
        int nt = dir ? nm : nf;
        const float4* __restrict__ tgt = g_sort[dir];
        const float4* __restrict__ qb  = g_sort[1 - dir];
        for (int w = gw; w < cnt; w += nwarps) {
            float4 q = qb[g_defer[dir][w]];
            float best = INFF;
            for (int p = lane; p < nt; p += 32) {
                float4 t = tgt[p];
                float ax = t.x - q.x, ay = t.y - q.y, az = t.z - q.z;
                float d2 = fmaf(ax, ax, fmaf(ay, ay, az * az));
                best = fminf(best, d2);
            }
#pragma unroll
            for (int o = 16; o; o >>= 1)
                best = fminf(best, __shfl_down_sync(0xffffffffu, best, o));
            if (lane == 0) atomicAdd(out, best / (float)nq);
        }
    }
}

// ---------------------------------------------------------------------------
extern "C" void kernel_launch(void* const* d_in, const int* in_sizes, int n_in,
                              void* d_out, int out_size) {
    const float* fx  = (const float*)d_in[0];
    const float* mv  = (const float*)d_in[1];
    const float* mat = (const float*)d_in[2];
    const float* tr  = (const float*)d_in[3];
    float* out = (float*)d_out;

    int nf = in_sizes[0] / 3;
    int nm = in_sizes[1] / 3;
    int nmax = nf > nm ? nf : nm;
    int pblk = (nmax + 255) / 256;
    if (pblk > 128) pblk = 128;

    prep_kernel<<<pblk, 256>>>(fx, mv, mat, tr, nf, nm, out, pblk);
    grid_kernel<<<1, 384>>>(pblk);
    count_kernel<<<pblk, 256>>>(nf, nm);
    scan1_kernel<<<dim3(SBLK, 2), 256>>>();
    scan2_kernel<<<1, SBLK>>>();
    scan3_kernel<<<dim3(SBLK, 2), 256>>>();
    scatter_kernel<<<pblk, 256>>>(nf, nm);
    query_kernel<<<dim3((nmax + 127) / 128, 2), 128>>>(out, nm, nf);
    brute_kernel<<<64, 256>>>(out, nm, nf);
}

// round 5
// speedup vs baseline: 70.9782x; 1.0965x over previous
#include <cuda_runtime.h>
#include <math_constants.h>

// ---------------------------------------------------------------------------
// AffineChamferLoss via EXACT uniform-grid NN over a ROBUST (mean +/- 3 sigma)
// grid. Outliers are clamped into boundary cells, which are treated as
// unbounded outward in all distance lower bounds -> search stays exact and
// every query's home cell sits at the dense-cloud surface (no stragglers).
// ---------------------------------------------------------------------------

#define NMAX  16384
#define CAP   65536           // cells per set
#define SBLK  64              // scan blocks per set (CAP/1024)
#define SPAD  (CAP + 16)
#define INFF  3.0e38f
#define RCAP  8               // safety cap before deferring to brute force

__device__ float4   g_xbuf[NMAX];          // transformed moving pts (set 1)
__device__ float4   g_ybuf[NMAX];          // fixed pts              (set 0)
__device__ int      g_cell[2][NMAX];
__device__ unsigned g_cnt[2][CAP];
__device__ int      g_startArr[2][SPAD];
__device__ unsigned g_cur[2][CAP];
__device__ float4   g_sort[2][NMAX];
__device__ float    g_mpart[2][128][6];    // per-block sums: sx,sy,sz,sxx,syy,szz
__device__ unsigned g_bsum[2][SBLK];
__device__ unsigned g_bscan[2][SBLK];
__device__ int      g_defer[2][NMAX];
__device__ int      g_dcount[2];

struct GridI { float mnx, mny, mnz, h, invh; int gx, gy, gz, pad; };
__device__ GridI g_grid[2];

// ---- 256-thread block exclusive scan ---------------------------------------
__device__ __forceinline__ unsigned excl_scan_256(unsigned v, unsigned* wsm) {
    int lane = threadIdx.x & 31, wp = threadIdx.x >> 5;
    unsigned inc = v;
#pragma unroll
    for (int o = 1; o < 32; o <<= 1) {
        unsigned n = __shfl_up_sync(0xffffffffu, inc, o);
        if (lane >= o) inc += n;
    }
    if (lane == 31) wsm[wp] = inc;
    __syncthreads();
    if (wp == 0) {
        unsigned ws = (lane < 8) ? wsm[lane] : 0u;
#pragma unroll
        for (int o = 1; o < 8; o <<= 1) {
            unsigned n = __shfl_up_sync(0xffffffffu, ws, o);
            if (lane >= o) ws += n;
        }
        if (lane < 8) wsm[lane] = ws;
    }
    __syncthreads();
    unsigned off = wp ? wsm[wp - 1] : 0u;
    return off + inc - v;
}

// ---------------------------------------------------------------------------
// K1: transform + moment partials + zero counts/out/defer
__global__ void prep_kernel(const float* __restrict__ fx,
                            const float* __restrict__ mv,
                            const float* __restrict__ mat,
                            const float* __restrict__ tr,
                            int nf, int nm, float* out, int nblocks) {
    __shared__ float sm[12];
    int t = threadIdx.x;
    if (t < 12) sm[t] = 0.0f;
    __syncthreads();

    int i = blockIdx.x * 256 + t;

    float mx0 = 0.f, mx1 = 0.f, mx2 = 0.f, mq0 = 0.f, mq1 = 0.f, mq2 = 0.f;
    if (i < nm) {
        float p0 = mv[3*i+0], p1 = mv[3*i+1], p2 = mv[3*i+2];
        float x0 = fmaf(p2, mat[6], fmaf(p1, mat[3], fmaf(p0, mat[0], tr[0])));
        float x1 = fmaf(p2, mat[7], fmaf(p1, mat[4], fmaf(p0, mat[1], tr[1])));
        float x2 = fmaf(p2, mat[8], fmaf(p1, mat[5], fmaf(p0, mat[2], tr[2])));
        g_xbuf[i] = make_float4(x0, x1, x2, 0.0f);
        mx0 = x0; mx1 = x1; mx2 = x2;
        mq0 = x0 * x0; mq1 = x1 * x1; mq2 = x2 * x2;
    }
    float fy0 = 0.f, fy1 = 0.f, fy2 = 0.f, fq0 = 0.f, fq1 = 0.f, fq2 = 0.f;
    if (i < nf) {
        float y0 = fx[3*i+0], y1 = fx[3*i+1], y2 = fx[3*i+2];
        g_ybuf[i] = make_float4(y0, y1, y2, 0.0f);
        fy0 = y0; fy1 = y1; fy2 = y2;
        fq0 = y0 * y0; fq1 = y1 * y1; fq2 = y2 * y2;
    }

    // warp sums -> smem atomics
    float vals[12] = {fy0, fy1, fy2, fq0, fq1, fq2, mx0, mx1, mx2, mq0, mq1, mq2};
#pragma unroll
    for (int a = 0; a < 12; a++) {
        float v = vals[a];
#pragma unroll
        for (int o = 16; o; o >>= 1) v += __shfl_down_sync(0xffffffffu, v, o);
        if ((t & 31) == 0) atomicAdd(&sm[a], v);
    }
    __syncthreads();
    if (t < 12) g_mpart[t / 6][blockIdx.x][t % 6] = sm[t];

    unsigned* cn = &g_cnt[0][0];
    int tid = blockIdx.x * 256 + t;
    int stride = nblocks * 256;
    for (int k = tid; k < 2 * CAP; k += stride) cn[k] = 0u;
    if (tid == 0) { out[0] = 0.0f; g_dcount[0] = 0; g_dcount[1] = 0; }
}

// K2: reduce moment partials, build robust grid geometry (384 threads)
__global__ void grid_kernel(int nblocks, int nf, int nm) {
    __shared__ float bb[12];
    int t = threadIdx.x;
    int slot = t >> 5, lane = t & 31;
    if (slot < 12) {
        int s = slot / 6, k = slot % 6;
        float v = 0.0f;
        for (int j = lane; j < nblocks; j += 32) v += g_mpart[s][j][k];
#pragma unroll
        for (int o = 16; o; o >>= 1) v += __shfl_down_sync(0xffffffffu, v, o);
        if (lane == 0) bb[slot] = v;
    }
    __syncthreads();
    if (t < 2) {
        int s = t;
        float n = (float)(s ? nm : nf);
        float inv = 1.0f / n;
        float mean[3], sig[3];
#pragma unroll
        for (int a = 0; a < 3; a++) {
            mean[a] = bb[s*6+a] * inv;
            float var = bb[s*6+3+a] * inv - mean[a] * mean[a];
            sig[a] = sqrtf(fmaxf(var, 1e-8f));
        }
        float ex = 6.0f * sig[0], ey = 6.0f * sig[1], ez = 6.0f * sig[2];
        float h = cbrtf(ex * ey * ez * (1.0f / (0.75f * (float)CAP)));
        int gx = 1, gy = 1, gz = 1;
        for (int it = 0; it < 48; ++it) {
            gx = (int)(ex / h) + 1;
            gy = (int)(ey / h) + 1;
            gz = (int)(ez / h) + 1;
            if ((long long)gx * (long long)gy * (long long)gz <= (long long)CAP) break;
            h *= 1.12f;
        }
        GridI gi;
        gi.mnx = mean[0] - 3.0f * sig[0];
        gi.mny = mean[1] - 3.0f * sig[1];
        gi.mnz = mean[2] - 3.0f * sig[2];
        gi.h = h; gi.invh = 1.0f / h;
        gi.gx = gx; gi.gy = gy; gi.gz = gz; gi.pad = 0;
        g_grid[s] = gi;
    }
}

// K3: cell ids + counts (clamped binning)
__global__ void count_kernel(int nf, int nm) {
    int i = blockIdx.x * blockDim.x + threadIdx.x;
    GridI a = g_grid[0], b = g_grid[1];
    if (i < nf) {
        float4 p = g_ybuf[i];
        int ix = min(a.gx - 1, max(0, (int)floorf((p.x - a.mnx) * a.invh)));
        int iy = min(a.gy - 1, max(0, (int)floorf((p.y - a.mny) * a.invh)));
        int iz = min(a.gz - 1, max(0, (int)floorf((p.z - a.mnz) * a.invh)));
        int c = (ix * a.gy + iy) * a.gz + iz;
        g_cell[0][i] = c;
        atomicAdd(&g_cnt[0][c], 1u);
    }
    if (i < nm) {
        float4 p = g_xbuf[i];
        int ix = min(b.gx - 1, max(0, (int)floorf((p.x - b.mnx) * b.invh)));
        int iy = min(b.gy - 1, max(0, (int)floorf((p.y - b.mny) * b.invh)));
        int iz = min(b.gz - 1, max(0, (int)floorf((p.z - b.mnz) * b.invh)));
        int c = (ix * b.gy + iy) * b.gz + iz;
        g_cell[1][i] = c;
        atomicAdd(&g_cnt[1][c], 1u);
    }
}

// K4: per-block sums (grid SBLK x 2, 256 threads, 1024 counts/block)
__global__ void scan1_kernel() {
    __shared__ unsigned sm[8];
    int s = blockIdx.y;
    const uint4* c4 = reinterpret_cast<const uint4*>(&g_cnt[s][0]);
    uint4 v = c4[blockIdx.x * 256 + threadIdx.x];
    unsigned tot = v.x + v.y + v.z + v.w;
    int lane = threadIdx.x & 31, wp = threadIdx.x >> 5;
#pragma unroll
    for (int o = 16; o; o >>= 1) tot += __shfl_down_sync(0xffffffffu, tot, o);
    if (lane == 0) sm[wp] = tot;
    __syncthreads();
    if (wp == 0) {
        unsigned w = (lane < 8) ? sm[lane] : 0u;
#pragma unroll
        for (int o = 4; o; o >>= 1) w += __shfl_down_sync(0xffffffffu, w, o);
        if (lane == 0) g_bsum[s][blockIdx.x] = w;
    }
}

// K5: scan SBLK block sums per set (1 block, 64 threads, 2 warps)
__global__ void scan2_kernel() {
    __shared__ unsigned wsm[2];
    int lane = threadIdx.x & 31, wp = threadIdx.x >> 5;
    for (int s = 0; s < 2; ++s) {
        unsigned v = g_bsum[s][threadIdx.x];
        unsigned inc = v;
#pragma unroll
        for (int o = 1; o < 32; o <<= 1) {
            unsigned n = __shfl_up_sync(0xffffffffu, inc, o);
            if (lane >= o) inc += n;
        }
        if (lane == 31) wsm[wp] = inc;
        __syncthreads();
        unsigned off = (wp == 1) ? wsm[0] : 0u;
        unsigned e = off + inc - v;
        g_bscan[s][threadIdx.x] = e;
        if (threadIdx.x == SBLK - 1) g_startArr[s][CAP] = (int)(e + v);
        __syncthreads();
    }
}

// K6: local scans + write starts & cursors
__global__ void scan3_kernel() {
    __shared__ unsigned wsm[8];
    int s = blockIdx.y;
    const uint4* c4 = reinterpret_cast<const uint4*>(&g_cnt[s][0]);
    int vi = blockIdx.x * 256 + threadIdx.x;
    uint4 v = c4[vi];
    unsigned p1 = v.x, p2 = v.x + v.y, p3 = p2 + v.z, tot = p3 + v.w;
    unsigned e = excl_scan_256(tot, wsm);
    unsigned off = g_bscan[s][blockIdx.x] + e;
    int4 st = make_int4((int)off, (int)(off + p1), (int)(off + p2), (int)(off + p3));
    reinterpret_cast<int4*>(&g_startArr[s][0])[vi] = st;
    reinterpret_cast<int4*>(&g_cur[s][0])[vi] = make_int4(st.x, st.y, st.z, st.w);
}

// K7: scatter into CSR order
__global__ void scatter_kernel(int nf, int nm) {
    int i = blockIdx.x * blockDim.x + threadIdx.x;
    if (i < nf) {
        int c = g_cell[0][i];
        unsigned p = atomicAdd(&g_cur[0][c], 1u);
        g_sort[0][p] = g_ybuf[i];
    }
    if (i < nm) {
        int c = g_cell[1][i];
        unsigned p = atomicAdd(&g_cur[1][c], 1u);
        g_sort[1][p] = g_xbuf[i];
    }
}

// Per-axis distance from q to cell i; boundary cells are unbounded outward
// (clamped outlier points may lie outside the nominal cell extent).
__device__ __forceinline__ float axdist(float q, float mn, float h, int i, int g) {
    float lo = fmaf((float)i, h, mn);
    float dl = (i > 0)     ? (lo - q)          : -INFF;  // q left of cell
    float dr = (i < g - 1) ? (q - (lo + h))    : -INFF;  // q right of cell
    return fmaxf(0.0f, fmaxf(dl, dr));
}

// K8: exact NN (ring-capped for safety) + mean reduction
__global__ void __launch_bounds__(128)
query_kernel(float* out, int nm, int nf) {
    const int dir = blockIdx.y;
    const int nq = dir ? nf : nm;
    const float4* __restrict__ qb  = g_sort[1 - dir];
    const float4* __restrict__ tgt = g_sort[dir];
    const int*    __restrict__ cs  = &g_startArr[dir][0];
    GridI gi = g_grid[dir];

    int qi = blockIdx.x * 128 + threadIdx.x;
    float acc = 0.0f;
    if (qi < nq) {
        float4 q = qb[qi];
        int cx = min(gi.gx - 1, max(0, (int)floorf((q.x - gi.mnx) * gi.invh)));
        int cy = min(gi.gy - 1, max(0, (int)floorf((q.y - gi.mny) * gi.invh)));
        int cz = min(gi.gz - 1, max(0, (int)floorf((q.z - gi.mnz) * gi.invh)));
        int rmx = max(max(max(cx, gi.gx - 1 - cx), max(cy, gi.gy - 1 - cy)),
                      max(cz, gi.gz - 1 - cz));

        float best = INFF;
        bool deferred = false;
        for (int r = 0;; ++r) {
            if (r >= 1) {
                // min distance from q to any point in cells outside scanned box
                int rm1 = r - 1;
                float bnd = INFF;
                if (cx - rm1 > 0)
                    bnd = fminf(bnd, q.x - fmaf((float)(cx - rm1), gi.h, gi.mnx));
                if (cx + rm1 < gi.gx - 1)
                    bnd = fminf(bnd, fmaf((float)(cx + rm1 + 1), gi.h, gi.mnx) - q.x);
                if (cy - rm1 > 0)
                    bnd = fminf(bnd, q.y - fmaf((float)(cy - rm1), gi.h, gi.mny));
                if (cy + rm1 < gi.gy - 1)
                    bnd = fminf(bnd, fmaf((float)(cy + rm1 + 1), gi.h, gi.mny) - q.y);
                if (cz - rm1 > 0)
                    bnd = fminf(bnd, q.z - fmaf((float)(cz - rm1), gi.h, gi.mnz));
                if (cz + rm1 < gi.gz - 1)
                    bnd = fminf(bnd, fmaf((float)(cz + rm1 + 1), gi.h, gi.mnz) - q.z);
                if (bnd * bnd >= best) break;   // exact termination (INF when done)
            }
            if (r > rmx) break;
            if (r > RCAP) { deferred = true; break; }

            int xlo = max(cx - r, 0), xhi = min(cx + r, gi.gx - 1);
            for (int ix = xlo; ix <= xhi; ++ix) {
                int adx = abs(ix - cx);
                float ddx = axdist(q.x, gi.mnx, gi.h, ix, gi.gx);
                float dx2 = ddx * ddx;
                if (dx2 >= best) continue;
                int ylo = max(cy - r, 0), yhi = min(cy + r, gi.gy - 1);
                for (int iy = ylo; iy <= yhi; ++iy) {
                    int ady = max(adx, abs(iy - cy));
                    float ddy = axdist(q.y, gi.mny, gi.h, iy, gi.gy);
                    float dxy2 = fmaf(ddy, ddy, dx2);
                    if (dxy2 >= best) continue;
                    int base = (ix * gi.gy + iy) * gi.gz;
                    if (ady == r) {
                        int zlo = max(cz - r, 0), zhi = min(cz + r, gi.gz - 1);
                        int s0 = cs[base + zlo], e0 = cs[base + zhi + 1];
                        for (int p = s0; p < e0; ++p) {
                            float4 tp = tgt[p];
                            float ax = tp.x - q.x, ay = tp.y - q.y, az = tp.z - q.z;
                            float d2 = fmaf(ax, ax, fmaf(ay, ay, az * az));
                            best = fminf(best, d2);
                        }
                    } else {
                        int zc = cz - r;
                        if (zc >= 0) {
                            float ddz = axdist(q.z, gi.mnz, gi.h, zc, gi.gz);
                            if (fmaf(ddz, ddz, dxy2) < best) {
                                int s0 = cs[base + zc], e0 = cs[base + zc + 1];
                                for (int p = s0; p < e0; ++p) {
                                    float4 tp = tgt[p];
                                    float ax = tp.x - q.x, ay = tp.y - q.y, az = tp.z - q.z;
                                    float d2 = fmaf(ax, ax, fmaf(ay, ay, az * az));
                                    best = fminf(best, d2);
                                }
                            }
                        }
                        zc = cz + r;
                        if (zc <= gi.gz - 1) {
                            float ddz = axdist(q.z, gi.mnz, gi.h, zc, gi.gz);
                            if (fmaf(ddz, ddz, dxy2) < best) {
                                int s0 = cs[base + zc], e0 = cs[base + zc + 1];
                                for (int p = s0; p < e0; ++p) {
                                    float4 tp = tgt[p];
                                    float ax = tp.x - q.x, ay = tp.y - q.y, az = tp.z - q.z;
                                    float d2 = fmaf(ax, ax, fmaf(ay, ay, az * az));
                                    best = fminf(best, d2);
                                }
                            }
                        }
                    }
                }
            }
        }
        if (deferred) {
            int slot = atomicAdd(&g_dcount[dir], 1);
            g_defer[dir][slot] = qi;
            acc = 0.0f;
        } else {
            acc = best / (float)nq;
        }
    }

#pragma unroll
    for (int o = 16; o; o >>= 1) acc += __shfl_down_sync(0xffffffffu, acc, o);
    __shared__ float ws[4];
    int lane = threadIdx.x & 31, warp = threadIdx.x >> 5;
    if (lane == 0) ws[warp] = acc;
    __syncthreads();
    if (warp == 0) {
        acc = (lane < 4) ? ws[lane] : 0.0f;
#pragma unroll
        for (int o = 2; o; o >>= 1) acc += __shfl_down_sync(0xffffffffu, acc, o);
        if (lane == 0) atomicAdd(out, acc);
    }
}

// K9: warp-per-query exhaustive NN for deferred queries (safety net)
__global__ void __launch_bounds__(256)
brute_kernel(float* out, int nm, int nf) {
    int gw = (blockIdx.x * 256 + threadIdx.x) >> 5;
    int lane = threadIdx.x & 31;
    int nwarps = (gridDim.x * 256) >> 5;
    for (int dir = 0; dir < 2; ++dir) {
        int cnt = g_dcount[dir];
        int nq = dir ? nf : nm;
        int nt = dir ? nm : nf;
        const float4* __restrict__ tgt = g_sort[dir];
        const float4* __restrict__ qb  = g_sort[1 - dir];
        for (int w = gw; w < cnt; w += nwarps) {
            float4 q = qb[g_defer[dir][w]];
            float best = INFF;
            for (int p = lane; p < nt; p += 32) {
                float4 t = tgt[p];
                float ax = t.x - q.x, ay = t.y - q.y, az = t.z - q.z;
                float d2 = fmaf(ax, ax, fmaf(ay, ay, az * az));
                best = fminf(best, d2);
            }
#pragma unroll
            for (int o = 16; o; o >>= 1)
                best = fminf(best, __shfl_down_sync(0xffffffffu, best, o));
            if (lane == 0) atomicAdd(out, best / (float)nq);
        }
    }
}

// ---------------------------------------------------------------------------
extern "C" void kernel_launch(void* const* d_in, const int* in_sizes, int n_in,
                              void* d_out, int out_size) {
    const float* fx  = (const float*)d_in[0];
    const float* mv  = (const float*)d_in[1];
    const float* mat = (const float*)d_in[2];
    const float* tr  = (const float*)d_in[3];
    float* out = (float*)d_out;

    int nf = in_sizes[0] / 3;
    int nm = in_sizes[1] / 3;
    int nmax = nf > nm ? nf : nm;
    int pblk = (nmax + 255) / 256;
    if (pblk > 128) pblk = 128;

    prep_kernel<<<pblk, 256>>>(fx, mv, mat, tr, nf, nm, out, pblk);
    grid_kernel<<<1, 384>>>(pblk, nf, nm);
    count_kernel<<<pblk, 256>>>(nf, nm);
    scan1_kernel<<<dim3(SBLK, 2), 256>>>();
    scan2_kernel<<<1, SBLK>>>();
    scan3_kernel<<<dim3(SBLK, 2), 256>>>();
    scatter_kernel<<<pblk, 256>>>(nf, nm);
    query_kernel<<<dim3((nmax + 127) / 128, 2), 128>>>(out, nm, nf);
    brute_kernel<<<64, 256>>>(out, nm, nf);
}

// round 6
// speedup vs baseline: 239.3295x; 3.3719x over previous
#include <cuda_runtime.h>
#include <math_constants.h>

// ---------------------------------------------------------------------------
// AffineChamferLoss: exact NN via anisotropic 32^3 linked-list grid.
// Phase 1: constant-work box scan (ring<=1, conditional ring-2 shell) with
//          exact slab termination proofs. Unproven queries -> defer list.
// Phase 2: warp-per-(query,chunk) exhaustive scan of deferred queries.
// All bounds exact (boundary cells open-ended outward for clamped outliers).
// ---------------------------------------------------------------------------

#define NMAX   16384
#define G      32            // grid cells per axis
#define CELLS  (G * G * G)   // 32768
#define INFF   3.0e38f
#define CH     2048          // brute chunk size
#define NCH    8             // chunks (NMAX / CH)

__device__ float4   g_xbuf[NMAX];          // transformed moving pts (set 1)
__device__ float4   g_ybuf[NMAX];          // fixed pts              (set 0)
__device__ float4   g_node[2][NMAX];       // per-set nodes: x,y,z,next(bits)
__device__ int      g_head[2][CELLS];
__device__ float    g_mpart[2][128][6];    // per-block sums sx..szz
__device__ int      g_defer[2][NMAX];
__device__ unsigned g_dbest[2][NMAX];      // ordered-uint best d2 per defer slot
__device__ int      g_dcount[2];

struct GridI {
    float mnx, mny, mnz;
    float hx, hy, hz;
    float ix, iy, iz;     // inverse h
};
__device__ GridI g_grid[2];

// ---- order-preserving float<->uint ----------------------------------------
__device__ __forceinline__ unsigned f2ord(float f) {
    unsigned u = __float_as_uint(f);
    return (u & 0x80000000u) ? ~u : (u | 0x80000000u);
}
__device__ __forceinline__ float ord2f(unsigned u) {
    return (u & 0x80000000u) ? __uint_as_float(u & 0x7fffffffu)
                             : __uint_as_float(~u);
}

// ---------------------------------------------------------------------------
// K1: transform + moment partials + zero heads/out/dcount
__global__ void prep_kernel(const float* __restrict__ fx,
                            const float* __restrict__ mv,
                            const float* __restrict__ mat,
                            const float* __restrict__ tr,
                            int nf, int nm, float* out, int nblocks) {
    __shared__ float sm[12];
    int t = threadIdx.x;
    if (t < 12) sm[t] = 0.0f;
    __syncthreads();

    int i = blockIdx.x * 256 + t;

    float mx0 = 0.f, mx1 = 0.f, mx2 = 0.f, mq0 = 0.f, mq1 = 0.f, mq2 = 0.f;
    if (i < nm) {
        float p0 = mv[3*i+0], p1 = mv[3*i+1], p2 = mv[3*i+2];
        float x0 = fmaf(p2, mat[6], fmaf(p1, mat[3], fmaf(p0, mat[0], tr[0])));
        float x1 = fmaf(p2, mat[7], fmaf(p1, mat[4], fmaf(p0, mat[1], tr[1])));
        float x2 = fmaf(p2, mat[8], fmaf(p1, mat[5], fmaf(p0, mat[2], tr[2])));
        g_xbuf[i] = make_float4(x0, x1, x2, 0.0f);
        mx0 = x0; mx1 = x1; mx2 = x2;
        mq0 = x0 * x0; mq1 = x1 * x1; mq2 = x2 * x2;
    }
    float fy0 = 0.f, fy1 = 0.f, fy2 = 0.f, fq0 = 0.f, fq1 = 0.f, fq2 = 0.f;
    if (i < nf) {
        float y0 = fx[3*i+0], y1 = fx[3*i+1], y2 = fx[3*i+2];
        g_ybuf[i] = make_float4(y0, y1, y2, 0.0f);
        fy0 = y0; fy1 = y1; fy2 = y2;
        fq0 = y0 * y0; fq1 = y1 * y1; fq2 = y2 * y2;
    }

    float vals[12] = {fy0, fy1, fy2, fq0, fq1, fq2, mx0, mx1, mx2, mq0, mq1, mq2};
#pragma unroll
    for (int a = 0; a < 12; a++) {
        float v = vals[a];
#pragma unroll
        for (int o = 16; o; o >>= 1) v += __shfl_down_sync(0xffffffffu, v, o);
        if ((t & 31) == 0) atomicAdd(&sm[a], v);
    }
    __syncthreads();
    if (t < 12) g_mpart[t / 6][blockIdx.x][t % 6] = sm[t];

    int* hd = &g_head[0][0];
    int tid = blockIdx.x * 256 + t;
    int stride = nblocks * 256;
    for (int k = tid; k < 2 * CELLS; k += stride) hd[k] = -1;
    if (tid == 0) { out[0] = 0.0f; g_dcount[0] = 0; g_dcount[1] = 0; }
}

// K2: reduce moment partials, build per-axis robust grid geometry
__global__ void grid_kernel(int nblocks, int nf, int nm) {
    __shared__ float bb[12];
    int t = threadIdx.x;
    int slot = t >> 5, lane = t & 31;
    if (slot < 12) {
        int s = slot / 6, k = slot % 6;
        float v = 0.0f;
        for (int j = lane; j < nblocks; j += 32) v += g_mpart[s][j][k];
#pragma unroll
        for (int o = 16; o; o >>= 1) v += __shfl_down_sync(0xffffffffu, v, o);
        if (lane == 0) bb[slot] = v;
    }
    __syncthreads();
    if (t < 2) {
        int s = t;
        float n = (float)(s ? nm : nf);
        float inv = 1.0f / n;
        float mean[3], sig[3];
#pragma unroll
        for (int a = 0; a < 3; a++) {
            mean[a] = bb[s*6+a] * inv;
            float var = bb[s*6+3+a] * inv - mean[a] * mean[a];
            sig[a] = sqrtf(fmaxf(var, 1e-8f));
        }
        GridI gi;
        gi.mnx = mean[0] - 3.0f * sig[0];
        gi.mny = mean[1] - 3.0f * sig[1];
        gi.mnz = mean[2] - 3.0f * sig[2];
        gi.hx = 6.0f * sig[0] / (float)G;
        gi.hy = 6.0f * sig[1] / (float)G;
        gi.hz = 6.0f * sig[2] / (float)G;
        gi.ix = 1.0f / gi.hx; gi.iy = 1.0f / gi.hy; gi.iz = 1.0f / gi.hz;
        g_grid[s] = gi;
    }
}

// K3: bin both sets into per-cell linked lists
__global__ void bin_kernel(int nf, int nm) {
    int i = blockIdx.x * blockDim.x + threadIdx.x;
    GridI a = g_grid[0], b = g_grid[1];
    if (i < nf) {
        float4 p = g_ybuf[i];
        int ix = min(G - 1, max(0, (int)floorf((p.x - a.mnx) * a.ix)));
        int iy = min(G - 1, max(0, (int)floorf((p.y - a.mny) * a.iy)));
        int iz = min(G - 1, max(0, (int)floorf((p.z - a.mnz) * a.iz)));
        int cell = (ix << 10) | (iy << 5) | iz;
        int old = atomicExch(&g_head[0][cell], i);
        g_node[0][i] = make_float4(p.x, p.y, p.z, __int_as_float(old));
    }
    if (i < nm) {
        float4 p = g_xbuf[i];
        int ix = min(G - 1, max(0, (int)floorf((p.x - b.mnx) * b.ix)));
        int iy = min(G - 1, max(0, (int)floorf((p.y - b.mny) * b.iy)));
        int iz = min(G - 1, max(0, (int)floorf((p.z - b.mnz) * b.iz)));
        int cell = (ix << 10) | (iy << 5) | iz;
        int old = atomicExch(&g_head[1][cell], i);
        g_node[1][i] = make_float4(p.x, p.y, p.z, __int_as_float(old));
    }
}

// per-axis distance from q to cell i (boundary cells open-ended outward)
__device__ __forceinline__ float axdist(float q, float mn, float h, int i) {
    float lo = fmaf((float)i, h, mn);
    float dl = (i > 0)     ? (lo - q)       : -INFF;
    float dr = (i < G - 1) ? (q - (lo + h)) : -INFF;
    return fmaxf(0.0f, fmaxf(dl, dr));
}

// exact min-distance to all cells OUTSIDE the scanned clipped box of radius R
__device__ __forceinline__ float slab_bound(float fr, float h, int c, int R) {
    float b = INFF;
    if (c - R >= 1)     b = fminf(b, h * (fr + (float)R));
    if (c + R <= G - 2) b = fminf(b, h * ((float)(R + 1) - fr));
    return b;
}

__device__ __forceinline__ void scan_cell(const float4* __restrict__ nd,
                                          const int* __restrict__ head,
                                          int cell, float4 q, float& best) {
    int idx = head[cell];
    while (idx >= 0) {
        float4 t = nd[idx];
        float ax = t.x - q.x, ay = t.y - q.y, az = t.z - q.z;
        float d2 = fmaf(ax, ax, fmaf(ay, ay, az * az));
        best = fminf(best, d2);
        idx = __float_as_int(t.w);
    }
}

// K4: constant-work exact NN (box R<=2) + mean reduction; unproven -> defer
__global__ void __launch_bounds__(256)
query_kernel(float* out, int nm, int nf) {
    const int dir = blockIdx.y;                 // 0: mov->fixed, 1: fixed->mov
    const int nq = dir ? nf : nm;
    const float4* __restrict__ qb   = dir ? g_ybuf    : g_xbuf;
    const float4* __restrict__ nd   = dir ? g_node[1] : g_node[0];
    const int*    __restrict__ head = dir ? g_head[1] : g_head[0];
    GridI gi = g_grid[dir];                     // grid of the TARGET set

    int qi = blockIdx.x * 256 + threadIdx.x;
    float acc = 0.0f;
    if (qi < nq) {
        float4 q = qb[qi];
        float rx = (q.x - gi.mnx) * gi.ix;
        float ry = (q.y - gi.mny) * gi.iy;
        float rz = (q.z - gi.mnz) * gi.iz;
        int cx = min(G - 1, max(0, (int)floorf(rx)));
        int cy = min(G - 1, max(0, (int)floorf(ry)));
        int cz = min(G - 1, max(0, (int)floorf(rz)));
        float fxr = rx - (float)cx;             // may be <0 or >1 if clamped
        float fyr = ry - (float)cy;
        float fzr = rz - (float)cz;

        float best = INFF;

        // ---- ring 0..1: scan clipped 3x3x3 box ----
        int xlo = max(cx - 1, 0), xhi = min(cx + 1, G - 1);
        int ylo = max(cy - 1, 0), yhi = min(cy + 1, G - 1);
        int zlo = max(cz - 1, 0), zhi = min(cz + 1, G - 1);
        for (int ix = xlo; ix <= xhi; ++ix)
            for (int iy = ylo; iy <= yhi; ++iy)
                for (int iz = zlo; iz <= zhi; ++iz)
                    scan_cell(nd, head, (ix << 10) | (iy << 5) | iz, q, best);

        float b1 = fminf(fminf(slab_bound(fxr, gi.hx, cx, 1),
                               slab_bound(fyr, gi.hy, cy, 1)),
                         slab_bound(fzr, gi.hz, cz, 1));
        bool done = (b1 * b1 >= best);

        if (!done) {
            // ---- ring 2 shell (clipped, per-cell pruned) ----
            int x2lo = max(cx - 2, 0), x2hi = min(cx + 2, G - 1);
            int y2lo = max(cy - 2, 0), y2hi = min(cy + 2, G - 1);
            for (int ix = x2lo; ix <= x2hi; ++ix) {
                int adx = abs(ix - cx);
                float ddx = axdist(q.x, gi.mnx, gi.hx, ix);
                float dx2 = ddx * ddx;
                if (dx2 >= best) continue;
                for (int iy = y2lo; iy <= y2hi; ++iy) {
                    int ad = max(adx, abs(iy - cy));
                    float ddy = axdist(q.y, gi.mny, gi.hy, iy);
                    float dxy2 = fmaf(ddy, ddy, dx2);
                    if (dxy2 >= best) continue;
                    int base = (ix << 10) | (iy << 5);
                    if (ad == 2) {
                        int z2lo = max(cz - 2, 0), z2hi = min(cz + 2, G - 1);
                        for (int iz = z2lo; iz <= z2hi; ++iz) {
                            float ddz = axdist(q.z, gi.mnz, gi.hz, iz);
                            if (fmaf(ddz, ddz, dxy2) < best)
                                scan_cell(nd, head, base | iz, q, best);
                        }
                    } else {
                        int zc = cz - 2;
                        if (zc >= 0) {
                            float ddz = axdist(q.z, gi.mnz, gi.hz, zc);
                            if (fmaf(ddz, ddz, dxy2) < best)
                                scan_cell(nd, head, base | zc, q, best);
                        }
                        zc = cz + 2;
                        if (zc <= G - 1) {
                            float ddz = axdist(q.z, gi.mnz, gi.hz, zc);
                            if (fmaf(ddz, ddz, dxy2) < best)
                                scan_cell(nd, head, base | zc, q, best);
                        }
                    }
                }
            }
            float b2 = fminf(fminf(slab_bound(fxr, gi.hx, cx, 2),
                                   slab_bound(fyr, gi.hy, cy, 2)),
                             slab_bound(fzr, gi.hz, cz, 2));
            done = (b2 * b2 >= best);
        }

        if (done) {
            acc = best / (float)nq;
        } else {
            int slot = atomicAdd(&g_dcount[dir], 1);
            g_defer[dir][slot] = qi;
            g_dbest[dir][slot] = f2ord(best);
        }
    }

#pragma unroll
    for (int o = 16; o; o >>= 1) acc += __shfl_down_sync(0xffffffffu, acc, o);
    __shared__ float ws[8];
    int lane = threadIdx.x & 31, warp = threadIdx.x >> 5;
    if (lane == 0) ws[warp] = acc;
    __syncthreads();
    if (warp == 0) {
        acc = (lane < 8) ? ws[lane] : 0.0f;
#pragma unroll
        for (int o = 4; o; o >>= 1) acc += __shfl_down_sync(0xffffffffu, acc, o);
        if (lane == 0) atomicAdd(out, acc);
    }
}

// K5: warp-per-(deferred query, target chunk) exhaustive scan
__global__ void __launch_bounds__(256)
brute_kernel(int nm, int nf) {
    int gw = (blockIdx.x * 256 + threadIdx.x) >> 5;
    int lane = threadIdx.x & 31;
    int nwarps = (gridDim.x * 256) >> 5;

    int cnt0 = min(g_dcount[0], NMAX);
    int cnt1 = min(g_dcount[1], NMAX);
    int items0 = cnt0 * NCH;
    int total = items0 + cnt1 * NCH;

    for (int it = gw; it < total; it += nwarps) {
        int dir = (it < items0) ? 0 : 1;
        int loc = (dir == 0) ? it : (it - items0);
        int slot = loc >> 3, ch = loc & (NCH - 1);
        int qi = g_defer[dir][slot];
        const float4* __restrict__ qb  = dir ? g_ybuf : g_xbuf;
        const float4* __restrict__ tb  = dir ? g_xbuf : g_ybuf;
        int nt = dir ? nm : nf;
        float4 q = qb[qi];
        int p1 = min(ch * CH + CH, nt);
        float best = INFF;
        for (int p = ch * CH + lane; p < p1; p += 32) {
            float4 t = tb[p];
            float ax = t.x - q.x, ay = t.y - q.y, az = t.z - q.z;
            float d2 = fmaf(ax, ax, fmaf(ay, ay, az * az));
            best = fminf(best, d2);
        }
#pragma unroll
        for (int o = 16; o; o >>= 1)
            best = fminf(best, __shfl_down_sync(0xffffffffu, best, o));
        if (lane == 0) atomicMin(&g_dbest[dir][slot], f2ord(best));
    }
}

// K6: sum deferred query means
__global__ void __launch_bounds__(256)
fin_kernel(float* out, int nm, int nf) {
    int cnt0 = min(g_dcount[0], NMAX);
    int cnt1 = min(g_dcount[1], NMAX);
    int total = cnt0 + cnt1;
    float acc = 0.0f;
    for (int i = blockIdx.x * 256 + threadIdx.x; i < total;
         i += gridDim.x * 256) {
        int dir = (i < cnt0) ? 0 : 1;
        int slot = (dir == 0) ? i : (i - cnt0);
        float nq = dir ? (float)nf : (float)nm;
        acc += ord2f(g_dbest[dir][slot]) / nq;
    }
#pragma unroll
    for (int o = 16; o; o >>= 1) acc += __shfl_down_sync(0xffffffffu, acc, o);
    __shared__ float ws[8];
    int lane = threadIdx.x & 31, warp = threadIdx.x >> 5;
    if (lane == 0) ws[warp] = acc;
    __syncthreads();
    if (warp == 0) {
        acc = (lane < 8) ? ws[lane] : 0.0f;
#pragma unroll
        for (int o = 4; o; o >>= 1) acc += __shfl_down_sync(0xffffffffu, acc, o);
        if (lane == 0) atomicAdd(out, acc);
    }
}

// ---------------------------------------------------------------------------
extern "C" void kernel_launch(void* const* d_in, const int* in_sizes, int n_in,
                              void* d_out, int out_size) {
    const float* fx  = (const float*)d_in[0];
    const float* mv  = (const float*)d_in[1];
    const float* mat = (const float*)d_in[2];
    const float* tr  = (const float*)d_in[3];
    float* out = (float*)d_out;

    int nf = in_sizes[0] / 3;
    int nm = in_sizes[1] / 3;
    int nmax = nf > nm ? nf : nm;
    int pblk = (nmax + 255) / 256;
    if (pblk > 128) pblk = 128;

    prep_kernel<<<pblk, 256>>>(fx, mv, mat, tr, nf, nm, out, pblk);
    grid_kernel<<<1, 384>>>(pblk, nf, nm);
    bin_kernel<<<pblk, 256>>>(nf, nm);
    query_kernel<<<dim3((nmax + 255) / 256, 2), 256>>>(out, nm, nf);
    brute_kernel<<<296, 256>>>(nm, nf);
    fin_kernel<<<32, 256>>>(out, nm, nf);
}